// round 16
// baseline (speedup 1.0000x reference)
#include <cuda_runtime.h>
#include <cstdint>

#define G 32           // groups
#define CG 2           // channels per group (C=64)
#define MAXB 1024      // max supported batch size for scratch sizing
#define EPSF 1e-5f
#define US 16          // stats: points per warp-iteration (MLP=16)
#define U 8            // normalize: points per warp-iteration
#define NSM 148        // sm count floor
#define BPSM 5

// Scratch (device globals: allocation-free per harness rules).
// Zero-initialized at load; the fused finalize (last stats block) self-resets
// everything it consumed, so every graph replay sees zeroed accumulators.
__device__ float  g_s1[MAXB * G];
__device__ float  g_s2[MAXB * G];
__device__ float  g_cnt[MAXB];
__device__ unsigned int g_done = 0;
__device__ __align__(16) float2 g_mi[MAXB * G];   // (mean, inv) per (b, g)

// packed helpers (f32x2 — PTX-only on sm_103a)
__device__ __forceinline__ unsigned long long pack_f32x2(float lo, float hi) {
    unsigned long long r;
    asm("mov.b64 %0, {%1, %2};" : "=l"(r) : "f"(lo), "f"(hi));
    return r;
}
__device__ __forceinline__ void unpack_f32x2(unsigned long long v, float& lo, float& hi) {
    asm("mov.b64 {%0, %1}, %2;" : "=f"(lo), "=f"(hi) : "l"(v));
}
__device__ __forceinline__ unsigned long long add_f32x2(unsigned long long a,
                                                        unsigned long long b) {
    unsigned long long r;
    asm("add.rn.f32x2 %0, %1, %2;" : "=l"(r) : "l"(a), "l"(b));
    return r;
}

// ---------------------------------------------------------------------------
// Kernel 1: stats (+ fused finalize) — R15 winner, byte-identical.
// Warp-per-point, lane L owns group L. US=16 front-batched LDG.64 (16 loads
// in flight per warp), binning through per-warp shared f32x2 accumulators.
// ---------------------------------------------------------------------------
__global__ void __launch_bounds__(256, BPSM) stats_kernel(const float* __restrict__ feat,
                                                          const int* __restrict__ bidx,
                                                          int N, const int* __restrict__ Bp) {
    const int B = *Bp;
    const int lane   = threadIdx.x & 31;
    const int wib    = threadIdx.x >> 5;           // warp in block (0..7)
    const int gwarp  = (blockIdx.x * blockDim.x + threadIdx.x) >> 5;
    const int nwarps = (gridDim.x * blockDim.x) >> 5;

    // per-warp bins: [warp][bin][lane], packed (s1,s2) as f32x2 in 8B
    __shared__ __align__(16) unsigned long long sh_acc[8][8][32];
    __shared__ float shc[8];

    if (B <= 8) {
#pragma unroll
        for (int bb = 0; bb < 8; bb++) sh_acc[wib][bb][lane] = 0ULL;
        float cnt = 0.0f;            // lane L accumulates count of bin L (L<8)

        unsigned long long* const mybins = &sh_acc[wib][0][lane];

        int base = gwarp * US;
        const int stride = nwarps * US;
        for (; base + (US - 1) < N; base += stride) {
            // phase 1: one lane-strided bidx load + 16 front-batched LDG.64
            const int myb = (lane < US) ? __ldg(bidx + base + lane) : 0;
            float2 xb[US];
#pragma unroll
            for (int j = 0; j < US; j++)
                xb[j] = __ldg(reinterpret_cast<const float2*>(
                              feat + (size_t)(base + j) * 64) + lane);
            // phase 2: bin through shared accumulators
#pragma unroll
            for (int j = 0; j < US; j++) {
                const int b = __shfl_sync(0xFFFFFFFFu, myb, j);
                const float v  = xb[j].x + xb[j].y;
                const float v2 = fmaf(xb[j].x, xb[j].x, xb[j].y * xb[j].y);
                unsigned long long* slot = mybins + b * 32;
                *slot = add_f32x2(*slot, pack_f32x2(v, v2));
                if (lane == b) cnt += 1.0f;
            }
        }
        // tail
        for (; base < N; base++) {
            const int b = __ldg(bidx + base);
            const float2 x = __ldg(reinterpret_cast<const float2*>(
                                   feat + (size_t)base * 64) + lane);
            unsigned long long* slot = mybins + b * 32;
            *slot = add_f32x2(*slot, pack_f32x2(x.x + x.y,
                                                fmaf(x.x, x.x, x.y * x.y)));
            if (lane == b) cnt += 1.0f;
        }

        // block reduction: accumulators already in shared.
        if (threadIdx.x < 8) shc[threadIdx.x] = 0.0f;
        __syncthreads();
        if (lane < 8 && cnt != 0.0f) atomicAdd(&shc[lane], cnt);
        __syncthreads();

        // thread i = bb*32+lane (exactly 256 threads): sum 8 warp slices
        {
            const int bb = threadIdx.x >> 5;   // bin
            const int ln = threadIdx.x & 31;   // lane/group
            float a1 = 0.0f, a2 = 0.0f;
#pragma unroll
            for (int wj = 0; wj < 8; wj++) {
                float p1, p2;
                unpack_f32x2(sh_acc[wj][bb][ln], p1, p2);
                a1 += p1; a2 += p2;
            }
            if (a1 != 0.0f || a2 != 0.0f) {
                atomicAdd(&g_s1[bb * G + ln], a1);
                atomicAdd(&g_s2[bb * G + ln], a2);
            }
        }
        if (threadIdx.x < 8 && shc[threadIdx.x] != 0.0f)
            atomicAdd(&g_cnt[threadIdx.x], shc[threadIdx.x]);
    } else {
        // Generic fallback: per-point global atomics (rare path)
        for (int p = gwarp; p < N; p += nwarps) {
            const int b = __ldg(bidx + p);
            if (b < 0 || b >= MAXB) continue;
            const float2 x = __ldg(reinterpret_cast<const float2*>(
                                   feat + (size_t)p * 64) + lane);
            atomicAdd(&g_s1[b * G + lane], x.x + x.y);
            atomicAdd(&g_s2[b * G + lane], fmaf(x.x, x.x, x.y * x.y));
            if (lane == 0) atomicAdd(&g_cnt[b], 1.0f);
        }
    }

    // ---- fused finalize: the last block to finish computes (mean, inv) and
    // resets all accumulators + the ticket for the next graph replay.
    __shared__ unsigned int s_ticket;
    __threadfence();
    if (threadIdx.x == 0) s_ticket = atomicAdd(&g_done, 1u);
    __syncthreads();
    if (s_ticket == (unsigned)(gridDim.x - 1)) {
        __threadfence();
        int BB = B < 1 ? 1 : (B > MAXB ? MAXB : B);
        for (int i2 = threadIdx.x; i2 < BB * G; i2 += blockDim.x) {
            const int b = i2 >> 5;
            const float c    = fmaxf(g_cnt[b] * (float)CG, 1.0f);
            const float mean = g_s1[i2] / c;
            const float var  = g_s2[i2] / c - mean * mean;
            const float inv  = rsqrtf(var + EPSF);
            g_mi[i2] = make_float2(mean, inv);
            g_s1[i2] = 0.0f;
            g_s2[i2] = 0.0f;
        }
        __syncthreads();
        for (int b = threadIdx.x; b < BB; b += blockDim.x) g_cnt[b] = 0.0f;
        if (threadIdx.x == 0) g_done = 0;
    }
}

// ---------------------------------------------------------------------------
// Kernel 2: normalize — R10 3-phase float2 reverse-sweep form, with the
// (mean,inv) table staged in SHARED memory (2KB, loaded once per block):
// phase-2 table reads become conflict-free LDS.64 and vanish from the
// L1tex wavefront queue (17 -> 9 LDG per 8 points).
//   out = (x - mean) * inv * w + bias
// ---------------------------------------------------------------------------
__global__ void __launch_bounds__(256, BPSM) normalize_kernel(const float* __restrict__ feat,
                                                              const int* __restrict__ bidx,
                                                              const float* __restrict__ w,
                                                              const float* __restrict__ bias,
                                                              float* __restrict__ out, int N,
                                                              const int* __restrict__ Bp) {
    const int B = *Bp;
    const int lane   = threadIdx.x & 31;
    const int gwarp  = (blockIdx.x * blockDim.x + threadIdx.x) >> 5;
    const int nwarps = (gridDim.x * blockDim.x) >> 5;

    const float2 wv = __ldg(reinterpret_cast<const float2*>(w) + lane);
    const float2 bv = __ldg(reinterpret_cast<const float2*>(bias) + lane);

    const int base0  = gwarp * U;
    const int stride = nwarps * U;

    int T = 0;
    if (base0 <= N - U) T = (N - U - base0) / stride + 1;

    if (B <= 8) {
        // stage the 256-entry (mean,inv) table into shared (one 8B per thread)
        __shared__ __align__(16) float2 sh_mi[8 * G];
        sh_mi[threadIdx.x] = g_mi[threadIdx.x];
        __syncthreads();

        // Tail first (at most one warp has a partial final chunk).
        for (int p = base0 + T * stride; p < N; p++) {
            const int b = __ldg(bidx + p);
            const float2 mi2 = sh_mi[b * G + lane];
            const float2 x = __ldcs(reinterpret_cast<const float2*>(
                                    feat + (size_t)p * 64) + lane);
            float2 y;
            y.x = fmaf(x.x - mi2.x, mi2.y * wv.x, bv.x);
            y.y = fmaf(x.y - mi2.x, mi2.y * wv.y, bv.y);
            __stcs(reinterpret_cast<float2*>(out + (size_t)p * 64) + lane, y);
        }

        // Main loop: descending chunk order (global back-to-front sweep).
        for (int t = T - 1; t >= 0; t--) {
            const int base = base0 + t * stride;
            const int myb = (lane < U) ? __ldg(bidx + base + lane) : 0;
            float2 xb[U];
#pragma unroll
            for (int j = 0; j < U; j++)
                xb[j] = __ldcs(reinterpret_cast<const float2*>(
                               feat + (size_t)(base + j) * 64) + lane);
            float2 mi[U];
#pragma unroll
            for (int j = 0; j < U; j++) {
                const int b = __shfl_sync(0xFFFFFFFFu, myb, j);
                mi[j] = sh_mi[b * G + lane];     // LDS.64, conflict-free
            }
#pragma unroll
            for (int j = 0; j < U; j++) {
                float2 y;
                y.x = fmaf(xb[j].x - mi[j].x, mi[j].y * wv.x, bv.x);
                y.y = fmaf(xb[j].y - mi[j].x, mi[j].y * wv.y, bv.y);
                __stcs(reinterpret_cast<float2*>(out + (size_t)(base + j) * 64) + lane, y);
            }
        }
    } else {
        // Generic path (B>8): global table (rare).
        for (int p = base0 + T * stride; p < N; p++) {
            const int b = __ldg(bidx + p);
            const float2 mi2 = __ldg(&g_mi[b * G + lane]);
            const float2 x = __ldcs(reinterpret_cast<const float2*>(
                                    feat + (size_t)p * 64) + lane);
            float2 y;
            y.x = fmaf(x.x - mi2.x, mi2.y * wv.x, bv.x);
            y.y = fmaf(x.y - mi2.x, mi2.y * wv.y, bv.y);
            __stcs(reinterpret_cast<float2*>(out + (size_t)p * 64) + lane, y);
        }
        for (int t = T - 1; t >= 0; t--) {
            const int base = base0 + t * stride;
            const int myb = (lane < U) ? __ldg(bidx + base + lane) : 0;
            float2 xb[U];
#pragma unroll
            for (int j = 0; j < U; j++)
                xb[j] = __ldcs(reinterpret_cast<const float2*>(
                               feat + (size_t)(base + j) * 64) + lane);
            float2 mi[U];
#pragma unroll
            for (int j = 0; j < U; j++) {
                const int b = __shfl_sync(0xFFFFFFFFu, myb, j);
                mi[j] = __ldg(&g_mi[b * G + lane]);
            }
#pragma unroll
            for (int j = 0; j < U; j++) {
                float2 y;
                y.x = fmaf(xb[j].x - mi[j].x, mi[j].y * wv.x, bv.x);
                y.y = fmaf(xb[j].y - mi[j].x, mi[j].y * wv.y, bv.y);
                __stcs(reinterpret_cast<float2*>(out + (size_t)(base + j) * 64) + lane, y);
            }
        }
    }
}

// ---------------------------------------------------------------------------
// kernel_launch
// inputs: 0=features [N*64] f32, 1=weight [64] f32, 2=bias [64] f32,
//         3=batch_idx [N] i32, 4=batch_size [1] i32 (device scalar)
// ---------------------------------------------------------------------------
extern "C" void kernel_launch(void* const* d_in, const int* in_sizes, int n_in,
                              void* d_out, int out_size) {
    const float* feat = (const float*)d_in[0];
    const float* w    = (const float*)d_in[1];
    const float* bias = (const float*)d_in[2];
    const int*   bidx = (const int*)d_in[3];
    const int*   Bp   = (const int*)d_in[4];
    float* out = (float*)d_out;

    const int N = in_sizes[3];           // batch_idx element count == N points

    const int threads = 256;

    // Stats: oversubscribed grid -> tail balancing (best measured).
    int stats_blocks = (N + 31) / 32;
    if (stats_blocks > 1184) stats_blocks = 1184;
    if (stats_blocks < 1) stats_blocks = 1;

    // Normalize: one resident wave (best measured).
    int norm_blocks = NSM * BPSM;        // 740
    int need = (N + 31) / 32;
    if (norm_blocks > need) norm_blocks = need;
    if (norm_blocks < 1) norm_blocks = 1;

    stats_kernel<<<stats_blocks, threads>>>(feat, bidx, N, Bp);
    normalize_kernel<<<norm_blocks, threads>>>(feat, bidx, w, bias, out, N, Bp);
}